// round 15
// baseline (speedup 1.0000x reference)
#include <cuda_runtime.h>
#include <cuda_fp16.h>
#include <math.h>
#include <stdint.h>

// Problem constants
#define Bb 8
#define Tt 4096
#define Cc 512
#define Kt 3
#define Ss 64

// Conv GEMM tiling: 128(M) x 128(N) CTA tile (proven best)
#define PITCH 72                         // fp16 elems per smem row (64 data + 8 pad)
#define TILE_BYTES (128 * PITCH * 2)     // 18432 B: one 128x64 fp16 tile
#define STAGE_BYTES (2 * TILE_BYTES)     // A, W
#define CONV_SMEM (2 * STAGE_BYTES)      // double buffered: 73728 B
#define NSTAGES 24                       // 3 taps x (512/64)

// ---------------- scratch (device globals; no runtime allocation) -------------
__device__ __half g_A  [(size_t)Bb * Tt * Cc];            // fp16 activations
__device__ __half g_T2h[(size_t)Bb * Tt * Cc];            // fp16 conv1 output
__device__ __half g_X1h[(size_t)Bb * Tt * Cc];            // fp16 residual trunk
__device__ __half g_W [(size_t)6 * Kt * Cc * Cc];         // [j][tap][cout][cin]
__device__ float g_SC[6 * Cc];
__device__ float g_GB[(size_t)6 * Bb * 2 * Cc];
__device__ float g_MU[Bb * Cc];
__device__ float g_RS[Bb * Cc];
__device__ float g_PS[2 * 128 * Bb * Cc];                 // per-slot partial sums/sumsq
__device__ float g_IA[6 * Cc];                            // 1/alpha per (block,layer)

// ================= PTX helpers (portable sm_80+ subset) ========================
__device__ __forceinline__ uint32_t smem_u32(const void* p) {
    uint32_t a;
    asm("{ .reg .u64 t; cvta.to.shared.u64 t, %1; cvt.u32.u64 %0, t; }" : "=r"(a) : "l"(p));
    return a;
}

__device__ __forceinline__ void mma16816(float* d, const uint32_t* a, const uint32_t* b) {
    asm volatile(
        "mma.sync.aligned.m16n8k16.row.col.f32.f16.f16.f32 "
        "{%0,%1,%2,%3}, {%4,%5,%6,%7}, {%8,%9}, {%0,%1,%2,%3};"
        : "+f"(d[0]), "+f"(d[1]), "+f"(d[2]), "+f"(d[3])
        : "r"(a[0]), "r"(a[1]), "r"(a[2]), "r"(a[3]), "r"(b[0]), "r"(b[1]));
}

__device__ __forceinline__ void ldsm4(uint32_t* r, uint32_t addr) {
    asm volatile("ldmatrix.sync.aligned.m8n8.x4.shared.b16 {%0,%1,%2,%3}, [%4];"
                 : "=r"(r[0]), "=r"(r[1]), "=r"(r[2]), "=r"(r[3]) : "r"(addr));
}

__device__ __forceinline__ void cp16(uint32_t dst, const void* src) {
    asm volatile("cp.async.cg.shared.global [%0], [%1], 16;" :: "r"(dst), "l"(src));
}
__device__ __forceinline__ void cp16z(uint32_t dst, const void* src, uint32_t n) {
    asm volatile("cp.async.cg.shared.global [%0], [%1], 16, %2;" :: "r"(dst), "l"(src), "r"(n));
}
#define CP_COMMIT() asm volatile("cp.async.commit_group;" ::: "memory")
#define CP_WAIT1()  asm volatile("cp.async.wait_group 1;" ::: "memory")
#define CP_WAIT0()  asm volatile("cp.async.wait_group 0;" ::: "memory")

// ---------------- fast sin^2 via FMA-pipe polynomial ---------------------------
__device__ __forceinline__ float sin2_poly(float x) {
    const float INVPI = 0.31830988618f;
    const float PI_HI = 3.14159274101f;
    const float PI_LO = -8.74227765734e-8f;
    float k = rintf(x * INVPI);
    float r = fmaf(k, -PI_HI, x);
    r = fmaf(k, -PI_LO, r);
    float t = r * r;
    float p = fmaf(t, 2.7557319e-6f, -1.9841270e-4f);
    p = fmaf(t, p, 8.3333338e-3f);
    p = fmaf(t, p, -1.6666667e-1f);
    p = fmaf(t, p, 1.0f);
    float s = r * p;
    return s * s;
}

// ---------------- fused setup: style MLP + weight-norm scale + 1/alpha ---------
__global__ void setup_kernel(const float* __restrict__ s,
                             const float* __restrict__ fc1w, const float* __restrict__ fc1b,
                             const float* __restrict__ fc2w, const float* __restrict__ fc2b,
                             const float* __restrict__ c1v, const float* __restrict__ c1g,
                             const float* __restrict__ c2v, const float* __restrict__ c2g,
                             const float* __restrict__ alpha1, const float* __restrict__ alpha2,
                             float* __restrict__ gb, float* __restrict__ sc,
                             float* __restrict__ ia)
{
    if (blockIdx.x < 48) {
        int j = blockIdx.x >> 3;
        int b = blockIdx.x & 7;
        int i = j >> 1, layer = j & 1;
        const float* w  = (layer ? fc2w : fc1w) + (size_t)i * Ss * 2 * Cc;
        const float* bi = (layer ? fc2b : fc1b) + (size_t)i * 2 * Cc;

        __shared__ float ss[Ss];
        if (threadIdx.x < Ss) ss[threadIdx.x] = s[b * Ss + threadIdx.x];
        __syncthreads();

        for (int n = threadIdx.x; n < 2 * Cc; n += blockDim.x) {
            float acc = bi[n];
#pragma unroll 8
            for (int k = 0; k < Ss; k++) acc += ss[k] * w[(size_t)k * 2 * Cc + n];
            gb[((size_t)j * Bb + b) * 2 * Cc + n] = acc;
        }
    } else {
        int j = blockIdx.x - 48, co = threadIdx.x;
        int i = j >> 1, layer = j & 1;
        const float* v = (layer ? c2v : c1v) + (size_t)i * Kt * Cc * Cc;
        const float* g = (layer ? c2g : c1g) + (size_t)i * Cc;
        float s0 = 0.f, s1 = 0.f;
#pragma unroll 4
        for (int r = 0; r < Kt * Cc; r += 2) {
            float t0 = v[(size_t)r * Cc + co];
            float t1 = v[(size_t)(r + 1) * Cc + co];
            s0 += t0 * t0; s1 += t1 * t1;
        }
        sc[j * Cc + co] = g[co] * rsqrtf(s0 + s1);
        const float* a = (layer ? alpha2 : alpha1) + (size_t)i * Cc;
        ia[j * Cc + co] = 1.0f / a[co];
    }
}

// ---------------- transpose weights to [j][tap][cout][cin] fp16 ----------------
__global__ void wtrans_kernel(const float* __restrict__ c1v, const float* __restrict__ c2v,
                              const float* __restrict__ sc, __half* __restrict__ wout)
{
    int bz = blockIdx.z;
    int j = bz / 3, tap = bz % 3;
    int i = j >> 1, layer = j & 1;
    const float* v = (layer ? c2v : c1v) + (((size_t)i * Kt + tap) * Cc) * Cc;
    int ci0 = blockIdx.x * 32, co0 = blockIdx.y * 32;

    __shared__ float tile[32][33];
#pragma unroll
    for (int q = 0; q < 4; q++) {
        int ci = ci0 + threadIdx.y + q * 8;
        int co = co0 + threadIdx.x;
        tile[threadIdx.y + q * 8][threadIdx.x] = v[(size_t)ci * Cc + co] * sc[j * Cc + co];
    }
    __syncthreads();
    size_t wb = ((size_t)(j * Kt + tap)) * Cc * Cc;
#pragma unroll
    for (int q = 0; q < 4; q++) {
        int co = co0 + threadIdx.y + q * 8;
        int ci = ci0 + threadIdx.x;
        wout[wb + (size_t)co * Cc + ci] = __float2half_rn(tile[threadIdx.x][threadIdx.y + q * 8]);
    }
}

// ---------------- initial stats partials on x (128 slots, dual chains) ---------
__global__ void initstats_kernel(const float* __restrict__ x, float* __restrict__ ps)
{
    int si = blockIdx.x;
    int b  = blockIdx.y;
    int c  = threadIdx.x;
    const float* p = x + (((size_t)b * Tt) + si * 32) * Cc + c;
    float S0 = 0.f, Q0 = 0.f, S1 = 0.f, Q1 = 0.f;
#pragma unroll 8
    for (int t = 0; t < 32; t += 2) {
        float v0 = p[(size_t)t * Cc];
        float v1 = p[(size_t)(t + 1) * Cc];
        S0 += v0; Q0 += v0 * v0;
        S1 += v1; Q1 += v1 * v1;
    }
    ps[((size_t)si * Bb + b) * Cc + c]         = S0 + S1;
    ps[((size_t)(128 + si) * Bb + b) * Cc + c] = Q0 + Q1;
}

// ---------------- finalize: 4 threads per output, shfl combine -----------------
template <int NSLOTS>
__global__ void finalize_kernel(const float* __restrict__ ps,
                                float* __restrict__ mu, float* __restrict__ rs)
{
    int gt  = blockIdx.x * 256 + threadIdx.x;     // 0..16383
    int idx = gt >> 2;                            // output 0..4095
    int part = gt & 3;
    int b = idx >> 9, c = idx & 511;
    const float* pS = ps + (size_t)b * Cc + c;
    constexpr int PER = NSLOTS / 4;
    float S = 0.f, S2 = 0.f;
#pragma unroll
    for (int q = 0; q < PER; q++) {
        int si = part * PER + q;
        S  += pS[(size_t)si * Bb * Cc];
        S2 += pS[(size_t)(NSLOTS + si) * Bb * Cc];
    }
    S  += __shfl_xor_sync(0xffffffffu, S, 1);
    S2 += __shfl_xor_sync(0xffffffffu, S2, 1);
    S  += __shfl_xor_sync(0xffffffffu, S, 2);
    S2 += __shfl_xor_sync(0xffffffffu, S2, 2);
    if (part == 0) {
        float m   = S * (1.0f / Tt);
        float var = S2 * (1.0f / Tt) - m * m;
        mu[idx] = m;
        rs[idx] = rsqrtf(var + 1e-5f);
    }
}

// ---------------- adain + snake (poly sin, no MUFU), 4 groups/thread -----------
template <bool IN_HALF>
__global__ void adain_snake_kernel(const void* __restrict__ xin,
                                   const float* __restrict__ mu, const float* __restrict__ rs,
                                   const float* __restrict__ gb,
                                   const float* __restrict__ alpha,
                                   const float* __restrict__ inva,
                                   __half* __restrict__ outh)
{
    const size_t base = (size_t)blockIdx.x * 1024 + threadIdx.x;

    // batched front loads (MLP ~4-12)
    float xv[4][4];
    uint2 rawh[4];
    float4 rawf[4];
#pragma unroll
    for (int q = 0; q < 4; q++) {
        size_t idx = base + q * 256;
        if (IN_HALF) rawh[q] = ((const uint2*)xin)[idx];
        else         rawf[q] = ((const float4*)xin)[idx];
    }
#pragma unroll
    for (int q = 0; q < 4; q++) {
        if (IN_HALF) {
            float2 f0 = __half22float2(*(__half2*)&rawh[q].x);
            float2 f1 = __half22float2(*(__half2*)&rawh[q].y);
            xv[q][0] = f0.x; xv[q][1] = f0.y; xv[q][2] = f1.x; xv[q][3] = f1.y;
        } else {
            xv[q][0] = rawf[q].x; xv[q][1] = rawf[q].y;
            xv[q][2] = rawf[q].z; xv[q][3] = rawf[q].w;
        }
    }

#pragma unroll
    for (int q = 0; q < 4; q++) {
        size_t idx = base + q * 256;
        size_t e = idx * 4;
        int c = (int)(e & (Cc - 1));
        int b = (int)(e >> 21);

        float4 gv = *(const float4*)(gb + (size_t)b * 2 * Cc + c);
        float4 bv = *(const float4*)(gb + (size_t)b * 2 * Cc + Cc + c);
        float4 mv = *(const float4*)(mu + b * Cc + c);
        float4 rv = *(const float4*)(rs + b * Cc + c);
        float4 av = *(const float4*)(alpha + c);
        float4 iv = *(const float4*)(inva + c);

        float o[4];
        {
            float v = (1.0f + gv.x) * ((xv[q][0] - mv.x) * rv.x) + bv.x;
            o[0] = fmaf(sin2_poly(av.x * v), iv.x, v);
        }
        {
            float v = (1.0f + gv.y) * ((xv[q][1] - mv.y) * rv.y) + bv.y;
            o[1] = fmaf(sin2_poly(av.y * v), iv.y, v);
        }
        {
            float v = (1.0f + gv.z) * ((xv[q][2] - mv.z) * rv.z) + bv.z;
            o[2] = fmaf(sin2_poly(av.z * v), iv.z, v);
        }
        {
            float v = (1.0f + gv.w) * ((xv[q][3] - mv.w) * rv.w) + bv.w;
            o[3] = fmaf(sin2_poly(av.w * v), iv.w, v);
        }

        uint32_t p0 = (uint32_t)__half_as_ushort(__float2half_rn(o[0])) |
                      ((uint32_t)__half_as_ushort(__float2half_rn(o[1])) << 16);
        uint32_t p1 = (uint32_t)__half_as_ushort(__float2half_rn(o[2])) |
                      ((uint32_t)__half_as_ushort(__float2half_rn(o[3])) << 16);
        ((uint2*)outh)[idx] = make_uint2(p0, p1);
    }
}

// ---------------- dilated conv: mma.sync fp16 GEMM, 128x128 tiles --------------
__device__ __forceinline__ void load_stage(uint32_t sdst,
    const __half* __restrict__ A, const __half* __restrict__ W,
    int bb, int t0, int tap, int kk, int dil, int block_n, int tid)
{
#pragma unroll
    for (int q = 0; q < 4; q++) {
        int c   = tid + 256 * q;
        int row = c >> 3, k8 = c & 7;
        int tp  = t0 + row + (tap - 1) * dil;
        bool valid = ((unsigned)tp < (unsigned)Tt);
        size_t off = (((size_t)bb << 12) + (size_t)(valid ? tp : 0)) * Cc + kk + k8 * 8;
        uint32_t dst = sdst + row * (PITCH * 2) + k8 * 16;
        cp16z(dst, A + off, valid ? 16u : 0u);
    }
#pragma unroll
    for (int q = 0; q < 4; q++) {
        int c   = tid + 256 * q;
        int row = c >> 3, k8 = c & 7;
        size_t off = ((size_t)(tap * Cc + block_n + row)) * Cc + kk + k8 * 8;
        cp16(sdst + TILE_BYTES + row * (PITCH * 2) + k8 * 16, W + off);
    }
}

template <bool OUT_HALF, bool RES_HALF>
__global__ void __launch_bounds__(256, 2)
conv_mma_kernel(const __half* __restrict__ A, const __half* __restrict__ W,
                const float* __restrict__ bias, const void* __restrict__ res,
                void* __restrict__ out, float* __restrict__ statsPart, int dil)
{
    extern __shared__ __align__(16) char dsm[];
    const uint32_t sbase = smem_u32(dsm);

    const int tid  = threadIdx.x;
    const int wid  = tid >> 5;
    const int lane = tid & 31;

    const int block_m = blockIdx.x * 128;
    const int block_n = blockIdx.y * 128;
    const int bb = block_m >> 12;
    const int t0 = block_m & (Tt - 1);

    const int wm = (wid >> 2) * 64;   // warp m offset (0 or 64)
    const int wn = (wid & 3) * 32;    // warp n offset (0..96)

    float acc[4][4][4];
#pragma unroll
    for (int i = 0; i < 4; i++)
#pragma unroll
        for (int j = 0; j < 4; j++)
#pragma unroll
            for (int r = 0; r < 4; r++) acc[i][j][r] = 0.f;

    // prologue: stage 0 into buffer 0
    load_stage(sbase, A, W, bb, t0, 0, 0, dil, block_n, tid);
    CP_COMMIT();

    for (int s = 0; s < NSTAGES; ++s) {
        const uint32_t sbuf = sbase + (uint32_t)(s & 1) * STAGE_BYTES;
        if (s + 1 < NSTAGES) {
            const int tap = (s + 1) >> 3;
            const int kk  = ((s + 1) & 7) << 6;
            load_stage(sbase + (uint32_t)((s + 1) & 1) * STAGE_BYTES,
                       A, W, bb, t0, tap, kk, dil, block_n, tid);
            CP_COMMIT();
            CP_WAIT1();
        } else {
            CP_WAIT0();
        }
        __syncthreads();

        const uint32_t sA = sbuf;
        const uint32_t sW = sbuf + TILE_BYTES;

        const int arow = lane & 15;
        const int ahalf = (lane >> 4) * 8;
        const int bn = (lane & 7) + ((lane >> 4) & 1) * 8;
        const int bk = ((lane >> 3) & 1) * 8;

#pragma unroll
        for (int ks = 0; ks < 4; ++ks) {
            const int kc = ks * 16;
            uint32_t ah[4][4], bh[2][4];
#pragma unroll
            for (int i = 0; i < 4; i++) {
                uint32_t aaddr = (uint32_t)((wm + i * 16 + arow) * (PITCH * 2) + (kc + ahalf) * 2);
                ldsm4(ah[i], sA + aaddr);
            }
#pragma unroll
            for (int j2 = 0; j2 < 2; j2++) {
                uint32_t baddr = (uint32_t)((wn + j2 * 16 + bn) * (PITCH * 2) + (kc + bk) * 2);
                ldsm4(bh[j2], sW + baddr);
            }
#pragma unroll
            for (int i = 0; i < 4; i++)
#pragma unroll
                for (int j = 0; j < 4; j++)
                    mma16816(acc[i][j], ah[i], &bh[j >> 1][(j & 1) * 2]);
        }
        __syncthreads();
    }

    // epilogue: bias (+ residual) + optional per-column stats partials
    float cs[4][2], cq[4][2];
#pragma unroll
    for (int j = 0; j < 4; j++) { cs[j][0] = cs[j][1] = cq[j][0] = cq[j][1] = 0.f; }

#pragma unroll
    for (int i = 0; i < 4; i++) {
#pragma unroll
        for (int j = 0; j < 4; j++) {
            const int col  = block_n + wn + j * 8 + (lane & 3) * 2;
            const int row0 = block_m + wm + i * 16 + (lane >> 2);
            const int row1 = row0 + 8;
            const float b0 = bias[col], b1 = bias[col + 1];

            float2 v0 = make_float2(acc[i][j][0] + b0, acc[i][j][1] + b1);
            float2 v1 = make_float2(acc[i][j][2] + b0, acc[i][j][3] + b1);
            if (res) {
                if (RES_HALF) {
                    const __half* rh = (const __half*)res;
                    float2 r0 = __half22float2(*(const __half2*)(rh + (size_t)row0 * Cc + col));
                    float2 r1 = __half22float2(*(const __half2*)(rh + (size_t)row1 * Cc + col));
                    v0.x += r0.x; v0.y += r0.y;
                    v1.x += r1.x; v1.y += r1.y;
                } else {
                    const float* rf = (const float*)res;
                    float2 r0 = *(const float2*)(rf + (size_t)row0 * Cc + col);
                    float2 r1 = *(const float2*)(rf + (size_t)row1 * Cc + col);
                    v0.x += r0.x; v0.y += r0.y;
                    v1.x += r1.x; v1.y += r1.y;
                }
            }
            if (OUT_HALF) {
                __half* oh = (__half*)out;
                *(__half2*)(oh + (size_t)row0 * Cc + col) = __floats2half2_rn(v0.x, v0.y);
                *(__half2*)(oh + (size_t)row1 * Cc + col) = __floats2half2_rn(v1.x, v1.y);
            } else {
                float* of = (float*)out;
                *(float2*)(of + (size_t)row0 * Cc + col) = v0;
                *(float2*)(of + (size_t)row1 * Cc + col) = v1;
            }

            cs[j][0] += v0.x + v1.x;
            cs[j][1] += v0.y + v1.y;
            cq[j][0] += v0.x * v0.x + v1.x * v1.x;
            cq[j][1] += v0.y * v0.y + v1.y * v1.y;
        }
    }

    if (statsPart) {
#pragma unroll
        for (int j = 0; j < 4; j++)
#pragma unroll
            for (int k = 0; k < 2; k++) {
#pragma unroll
                for (int off = 4; off < 32; off <<= 1) {
                    cs[j][k] += __shfl_xor_sync(0xffffffffu, cs[j][k], off);
                    cq[j][k] += __shfl_xor_sync(0xffffffffu, cq[j][k], off);
                }
            }
        float* ssum = (float*)dsm;          // [8][32]
        float* ssq  = ssum + 256;
        if (lane < 4) {
#pragma unroll
            for (int j = 0; j < 4; j++)
#pragma unroll
                for (int k = 0; k < 2; k++) {
                    int cc = j * 8 + lane * 2 + k;
                    ssum[wid * 32 + cc] = cs[j][k];
                    ssq [wid * 32 + cc] = cq[j][k];
                }
        }
        __syncthreads();
        const int si = (block_m >> 7) & 31;
        if (tid < 128) {
            int w = tid >> 5, cw = tid & 31;
            statsPart[((size_t)si * Bb + bb) * Cc + block_n + tid] =
                ssum[w * 32 + cw] + ssum[(w + 4) * 32 + cw];
        } else {
            int t2 = tid - 128;
            int w = t2 >> 5, cw = t2 & 31;
            statsPart[((size_t)(32 + si) * Bb + bb) * Cc + block_n + t2] =
                ssq[w * 32 + cw] + ssq[(w + 4) * 32 + cw];
        }
    }
}

// -------------------------------- launch --------------------------------------
extern "C" void kernel_launch(void* const* d_in, const int* in_sizes, int n_in,
                              void* d_out, int out_size)
{
    (void)in_sizes; (void)n_in; (void)out_size;
    const float* x      = (const float*)d_in[0];
    const float* s      = (const float*)d_in[1];
    const float* fc1w   = (const float*)d_in[2];
    const float* fc1b   = (const float*)d_in[3];
    const float* alpha1 = (const float*)d_in[4];
    const float* c1v    = (const float*)d_in[5];
    const float* c1g    = (const float*)d_in[6];
    const float* c1b    = (const float*)d_in[7];
    const float* fc2w   = (const float*)d_in[8];
    const float* fc2b   = (const float*)d_in[9];
    const float* alpha2 = (const float*)d_in[10];
    const float* c2v    = (const float*)d_in[11];
    const float* c2g    = (const float*)d_in[12];
    const float* c2b    = (const float*)d_in[13];
    float* out = (float*)d_out;

    __half *A, *T2h, *X1h, *W;
    float *SC, *GB, *MU, *RS, *PS, *IA;
    cudaGetSymbolAddress((void**)&A,   g_A);
    cudaGetSymbolAddress((void**)&T2h, g_T2h);
    cudaGetSymbolAddress((void**)&X1h, g_X1h);
    cudaGetSymbolAddress((void**)&W,   g_W);
    cudaGetSymbolAddress((void**)&SC,  g_SC);
    cudaGetSymbolAddress((void**)&GB,  g_GB);
    cudaGetSymbolAddress((void**)&MU,  g_MU);
    cudaGetSymbolAddress((void**)&RS,  g_RS);
    cudaGetSymbolAddress((void**)&PS,  g_PS);
    cudaGetSymbolAddress((void**)&IA,  g_IA);

    cudaFuncSetAttribute(conv_mma_kernel<true, false>,
                         cudaFuncAttributeMaxDynamicSharedMemorySize, CONV_SMEM);
    cudaFuncSetAttribute(conv_mma_kernel<true, true>,
                         cudaFuncAttributeMaxDynamicSharedMemorySize, CONV_SMEM);
    cudaFuncSetAttribute(conv_mma_kernel<false, true>,
                         cudaFuncAttributeMaxDynamicSharedMemorySize, CONV_SMEM);

    // setup: style affines + weight-norm scale + inv-alpha (one kernel), transpose
    setup_kernel<<<54, 512>>>(s, fc1w, fc1b, fc2w, fc2b,
                              c1v, c1g, c2v, c2g, alpha1, alpha2, GB, SC, IA);
    wtrans_kernel<<<dim3(16, 16, 18), dim3(32, 8)>>>(c1v, c2v, SC, W);

    const int dils[3] = {1, 3, 5};
    const size_t N4 = (size_t)Bb * Tt * Cc / 4;
    const int ew_blocks = (int)(N4 / 1024);         // 4 float4 per thread
    dim3 conv_grid((Bb * Tt) / 128, Cc / 128);
    const size_t KCC = (size_t)Kt * Cc * Cc;

    // initial stats on x
    initstats_kernel<<<dim3(128, Bb), 512>>>(x, PS);
    finalize_kernel<128><<<64, 256>>>(PS, MU, RS);

    for (int i = 0; i < 3; i++) {
        // ---- layer 1: adain -> conv(dil) into T2h (+stats) ----
        if (i == 0)
            adain_snake_kernel<false><<<ew_blocks, 256>>>(x, MU, RS,
                    GB + (size_t)(2 * i) * Bb * 2 * Cc,
                    alpha1 + (size_t)i * Cc, IA + (size_t)(2 * i) * Cc, A);
        else
            adain_snake_kernel<true><<<ew_blocks, 256>>>(X1h, MU, RS,
                    GB + (size_t)(2 * i) * Bb * 2 * Cc,
                    alpha1 + (size_t)i * Cc, IA + (size_t)(2 * i) * Cc, A);

        conv_mma_kernel<true, false><<<conv_grid, 256, CONV_SMEM>>>(A,
                W + (size_t)(2 * i) * KCC, c1b + (size_t)i * Cc,
                (const void*)0, T2h, PS, dils[i]);
        finalize_kernel<32><<<64, 256>>>(PS, MU, RS);

        // ---- layer 2: adain -> conv(1) + residual ----
        adain_snake_kernel<true><<<ew_blocks, 256>>>(T2h, MU, RS,
                GB + (size_t)(2 * i + 1) * Bb * 2 * Cc,
                alpha2 + (size_t)i * Cc, IA + (size_t)(2 * i + 1) * Cc, A);

        if (i == 0) {
            conv_mma_kernel<true, false><<<conv_grid, 256, CONV_SMEM>>>(A,
                    W + (size_t)(2 * i + 1) * KCC, c2b + (size_t)i * Cc,
                    (const void*)x, X1h, PS, 1);
            finalize_kernel<32><<<64, 256>>>(PS, MU, RS);
        } else if (i == 1) {
            conv_mma_kernel<true, true><<<conv_grid, 256, CONV_SMEM>>>(A,
                    W + (size_t)(2 * i + 1) * KCC, c2b + (size_t)i * Cc,
                    (const void*)X1h, X1h, PS, 1);
            finalize_kernel<32><<<64, 256>>>(PS, MU, RS);
        } else {
            conv_mma_kernel<false, true><<<conv_grid, 256, CONV_SMEM>>>(A,
                    W + (size_t)(2 * i + 1) * KCC, c2b + (size_t)i * Cc,
                    (const void*)X1h, out, (float*)0, 1);
        }
    }
}

// round 16
// speedup vs baseline: 1.0607x; 1.0607x over previous
#include <cuda_runtime.h>
#include <cuda_fp16.h>
#include <math.h>
#include <stdint.h>

// Problem constants
#define Bb 8
#define Tt 4096
#define Cc 512
#define Kt 3
#define Ss 64

// Conv GEMM tiling: 128(M) x 128(N) CTA tile, k-major stages with A reuse
#define PITCH 72                          // fp16 elems per smem row (64 data + 8 pad)
#define ROWB 144                          // bytes per smem row
#define ABUF_ROWS 138                     // 128 + 2*max_dil
#define A_STAGE (ABUF_ROWS * ROWB)        // 19872 B
#define W_STAGE (128 * ROWB)              // 18432 B
#define CONV_SMEM (2 * A_STAGE + 2 * W_STAGE)   // 76608 B

// ---------------- scratch (device globals; no runtime allocation) -------------
__device__ __half g_A  [(size_t)Bb * Tt * Cc];            // fp16 activations
__device__ __half g_T2h[(size_t)Bb * Tt * Cc];            // fp16 conv1 output
__device__ __half g_X1h[(size_t)Bb * Tt * Cc];            // fp16 residual trunk
__device__ __half g_W [(size_t)6 * Kt * Cc * Cc];         // [j][tap][cout][cin]
__device__ float g_SC[6 * Cc];
__device__ float g_GB[(size_t)6 * Bb * 2 * Cc];
__device__ float g_MU[Bb * Cc];
__device__ float g_RS[Bb * Cc];
__device__ float g_PS[2 * 128 * Bb * Cc];                 // per-slot partial sums/sumsq
__device__ float g_IA[6 * Cc];                            // 1/alpha per (block,layer)

// ================= PTX helpers (portable sm_80+ subset) ========================
__device__ __forceinline__ uint32_t smem_u32(const void* p) {
    uint32_t a;
    asm("{ .reg .u64 t; cvta.to.shared.u64 t, %1; cvt.u32.u64 %0, t; }" : "=r"(a) : "l"(p));
    return a;
}

__device__ __forceinline__ void mma16816(float* d, const uint32_t* a, const uint32_t* b) {
    asm volatile(
        "mma.sync.aligned.m16n8k16.row.col.f32.f16.f16.f32 "
        "{%0,%1,%2,%3}, {%4,%5,%6,%7}, {%8,%9}, {%0,%1,%2,%3};"
        : "+f"(d[0]), "+f"(d[1]), "+f"(d[2]), "+f"(d[3])
        : "r"(a[0]), "r"(a[1]), "r"(a[2]), "r"(a[3]), "r"(b[0]), "r"(b[1]));
}

__device__ __forceinline__ void ldsm4(uint32_t* r, uint32_t addr) {
    asm volatile("ldmatrix.sync.aligned.m8n8.x4.shared.b16 {%0,%1,%2,%3}, [%4];"
                 : "=r"(r[0]), "=r"(r[1]), "=r"(r[2]), "=r"(r[3]) : "r"(addr));
}

__device__ __forceinline__ void cp16(uint32_t dst, const void* src) {
    asm volatile("cp.async.cg.shared.global [%0], [%1], 16;" :: "r"(dst), "l"(src));
}
__device__ __forceinline__ void cp16z(uint32_t dst, const void* src, uint32_t n) {
    asm volatile("cp.async.cg.shared.global [%0], [%1], 16, %2;" :: "r"(dst), "l"(src), "r"(n));
}
#define CP_COMMIT() asm volatile("cp.async.commit_group;" ::: "memory")
#define CP_WAIT1()  asm volatile("cp.async.wait_group 1;" ::: "memory")
#define CP_WAIT0()  asm volatile("cp.async.wait_group 0;" ::: "memory")

// ---------------- fast sin^2 via FMA-pipe polynomial ---------------------------
__device__ __forceinline__ float sin2_poly(float x) {
    const float INVPI = 0.31830988618f;
    const float PI_HI = 3.14159274101f;
    const float PI_LO = -8.74227765734e-8f;
    float k = rintf(x * INVPI);
    float r = fmaf(k, -PI_HI, x);
    r = fmaf(k, -PI_LO, r);
    float t = r * r;
    float p = fmaf(t, 2.7557319e-6f, -1.9841270e-4f);
    p = fmaf(t, p, 8.3333338e-3f);
    p = fmaf(t, p, -1.6666667e-1f);
    p = fmaf(t, p, 1.0f);
    float s = r * p;
    return s * s;
}

// ---------------- fused setup: style MLP + weight-norm scale + 1/alpha ---------
__global__ void setup_kernel(const float* __restrict__ s,
                             const float* __restrict__ fc1w, const float* __restrict__ fc1b,
                             const float* __restrict__ fc2w, const float* __restrict__ fc2b,
                             const float* __restrict__ c1v, const float* __restrict__ c1g,
                             const float* __restrict__ c2v, const float* __restrict__ c2g,
                             const float* __restrict__ alpha1, const float* __restrict__ alpha2,
                             float* __restrict__ gb, float* __restrict__ sc,
                             float* __restrict__ ia)
{
    if (blockIdx.x < 48) {
        int j = blockIdx.x >> 3;
        int b = blockIdx.x & 7;
        int i = j >> 1, layer = j & 1;
        const float* w  = (layer ? fc2w : fc1w) + (size_t)i * Ss * 2 * Cc;
        const float* bi = (layer ? fc2b : fc1b) + (size_t)i * 2 * Cc;

        __shared__ float ss[Ss];
        if (threadIdx.x < Ss) ss[threadIdx.x] = s[b * Ss + threadIdx.x];
        __syncthreads();

        for (int n = threadIdx.x; n < 2 * Cc; n += blockDim.x) {
            float acc = bi[n];
#pragma unroll 8
            for (int k = 0; k < Ss; k++) acc += ss[k] * w[(size_t)k * 2 * Cc + n];
            gb[((size_t)j * Bb + b) * 2 * Cc + n] = acc;
        }
    } else {
        int j = blockIdx.x - 48, co = threadIdx.x;
        int i = j >> 1, layer = j & 1;
        const float* v = (layer ? c2v : c1v) + (size_t)i * Kt * Cc * Cc;
        const float* g = (layer ? c2g : c1g) + (size_t)i * Cc;
        float s0 = 0.f, s1 = 0.f;
#pragma unroll 4
        for (int r = 0; r < Kt * Cc; r += 2) {
            float t0 = v[(size_t)r * Cc + co];
            float t1 = v[(size_t)(r + 1) * Cc + co];
            s0 += t0 * t0; s1 += t1 * t1;
        }
        sc[j * Cc + co] = g[co] * rsqrtf(s0 + s1);
        const float* a = (layer ? alpha2 : alpha1) + (size_t)i * Cc;
        ia[j * Cc + co] = 1.0f / a[co];
    }
}

// ---------------- transpose weights to [j][tap][cout][cin] fp16 ----------------
__global__ void wtrans_kernel(const float* __restrict__ c1v, const float* __restrict__ c2v,
                              const float* __restrict__ sc, __half* __restrict__ wout)
{
    int bz = blockIdx.z;
    int j = bz / 3, tap = bz % 3;
    int i = j >> 1, layer = j & 1;
    const float* v = (layer ? c2v : c1v) + (((size_t)i * Kt + tap) * Cc) * Cc;
    int ci0 = blockIdx.x * 32, co0 = blockIdx.y * 32;

    __shared__ float tile[32][33];
#pragma unroll
    for (int q = 0; q < 4; q++) {
        int ci = ci0 + threadIdx.y + q * 8;
        int co = co0 + threadIdx.x;
        tile[threadIdx.y + q * 8][threadIdx.x] = v[(size_t)ci * Cc + co] * sc[j * Cc + co];
    }
    __syncthreads();
    size_t wb = ((size_t)(j * Kt + tap)) * Cc * Cc;
#pragma unroll
    for (int q = 0; q < 4; q++) {
        int co = co0 + threadIdx.y + q * 8;
        int ci = ci0 + threadIdx.x;
        wout[wb + (size_t)co * Cc + ci] = __float2half_rn(tile[threadIdx.x][threadIdx.y + q * 8]);
    }
}

// ---------------- initial stats partials on x (128 slots, dual chains) ---------
__global__ void initstats_kernel(const float* __restrict__ x, float* __restrict__ ps)
{
    int si = blockIdx.x;
    int b  = blockIdx.y;
    int c  = threadIdx.x;
    const float* p = x + (((size_t)b * Tt) + si * 32) * Cc + c;
    float S0 = 0.f, Q0 = 0.f, S1 = 0.f, Q1 = 0.f;
#pragma unroll 8
    for (int t = 0; t < 32; t += 2) {
        float v0 = p[(size_t)t * Cc];
        float v1 = p[(size_t)(t + 1) * Cc];
        S0 += v0; Q0 += v0 * v0;
        S1 += v1; Q1 += v1 * v1;
    }
    ps[((size_t)si * Bb + b) * Cc + c]         = S0 + S1;
    ps[((size_t)(128 + si) * Bb + b) * Cc + c] = Q0 + Q1;
}

// ---------------- finalize: 4 threads per output, shfl combine -----------------
template <int NSLOTS>
__global__ void finalize_kernel(const float* __restrict__ ps,
                                float* __restrict__ mu, float* __restrict__ rs)
{
    int gt  = blockIdx.x * 256 + threadIdx.x;
    int idx = gt >> 2;
    int part = gt & 3;
    int b = idx >> 9, c = idx & 511;
    const float* pS = ps + (size_t)b * Cc + c;
    constexpr int PER = NSLOTS / 4;
    float S = 0.f, S2 = 0.f;
#pragma unroll
    for (int q = 0; q < PER; q++) {
        int si = part * PER + q;
        S  += pS[(size_t)si * Bb * Cc];
        S2 += pS[(size_t)(NSLOTS + si) * Bb * Cc];
    }
    S  += __shfl_xor_sync(0xffffffffu, S, 1);
    S2 += __shfl_xor_sync(0xffffffffu, S2, 1);
    S  += __shfl_xor_sync(0xffffffffu, S, 2);
    S2 += __shfl_xor_sync(0xffffffffu, S2, 2);
    if (part == 0) {
        float m   = S * (1.0f / Tt);
        float var = S2 * (1.0f / Tt) - m * m;
        mu[idx] = m;
        rs[idx] = rsqrtf(var + 1e-5f);
    }
}

// ---------------- adain + snake (poly sin, no MUFU), 4 groups/thread -----------
template <bool IN_HALF>
__global__ void adain_snake_kernel(const void* __restrict__ xin,
                                   const float* __restrict__ mu, const float* __restrict__ rs,
                                   const float* __restrict__ gb,
                                   const float* __restrict__ alpha,
                                   const float* __restrict__ inva,
                                   __half* __restrict__ outh)
{
    const size_t base = (size_t)blockIdx.x * 1024 + threadIdx.x;

    float xv[4][4];
    uint2 rawh[4];
    float4 rawf[4];
#pragma unroll
    for (int q = 0; q < 4; q++) {
        size_t idx = base + q * 256;
        if (IN_HALF) rawh[q] = ((const uint2*)xin)[idx];
        else         rawf[q] = ((const float4*)xin)[idx];
    }
#pragma unroll
    for (int q = 0; q < 4; q++) {
        if (IN_HALF) {
            float2 f0 = __half22float2(*(__half2*)&rawh[q].x);
            float2 f1 = __half22float2(*(__half2*)&rawh[q].y);
            xv[q][0] = f0.x; xv[q][1] = f0.y; xv[q][2] = f1.x; xv[q][3] = f1.y;
        } else {
            xv[q][0] = rawf[q].x; xv[q][1] = rawf[q].y;
            xv[q][2] = rawf[q].z; xv[q][3] = rawf[q].w;
        }
    }

#pragma unroll
    for (int q = 0; q < 4; q++) {
        size_t idx = base + q * 256;
        size_t e = idx * 4;
        int c = (int)(e & (Cc - 1));
        int b = (int)(e >> 21);

        float4 gv = *(const float4*)(gb + (size_t)b * 2 * Cc + c);
        float4 bv = *(const float4*)(gb + (size_t)b * 2 * Cc + Cc + c);
        float4 mv = *(const float4*)(mu + b * Cc + c);
        float4 rv = *(const float4*)(rs + b * Cc + c);
        float4 av = *(const float4*)(alpha + c);
        float4 iv = *(const float4*)(inva + c);

        float o[4];
        {
            float v = (1.0f + gv.x) * ((xv[q][0] - mv.x) * rv.x) + bv.x;
            o[0] = fmaf(sin2_poly(av.x * v), iv.x, v);
        }
        {
            float v = (1.0f + gv.y) * ((xv[q][1] - mv.y) * rv.y) + bv.y;
            o[1] = fmaf(sin2_poly(av.y * v), iv.y, v);
        }
        {
            float v = (1.0f + gv.z) * ((xv[q][2] - mv.z) * rv.z) + bv.z;
            o[2] = fmaf(sin2_poly(av.z * v), iv.z, v);
        }
        {
            float v = (1.0f + gv.w) * ((xv[q][3] - mv.w) * rv.w) + bv.w;
            o[3] = fmaf(sin2_poly(av.w * v), iv.w, v);
        }

        uint32_t p0 = (uint32_t)__half_as_ushort(__float2half_rn(o[0])) |
                      ((uint32_t)__half_as_ushort(__float2half_rn(o[1])) << 16);
        uint32_t p1 = (uint32_t)__half_as_ushort(__float2half_rn(o[2])) |
                      ((uint32_t)__half_as_ushort(__float2half_rn(o[3])) << 16);
        ((uint2*)outh)[idx] = make_uint2(p0, p1);
    }
}

// ---------------- dilated conv: k-major stages, A reused across taps -----------
__device__ __forceinline__ void load_A_chunk(uint32_t adst, const __half* __restrict__ A,
    int bb, int t0, int kk, int dil, int tid)
{
    const int nops = (128 + 2 * dil) * 8;
    for (int it = tid; it < nops; it += 256) {
        int row = it >> 3, k8 = it & 7;
        int g = t0 - dil + row;
        bool valid = ((unsigned)g < (unsigned)Tt);
        size_t off = (((size_t)bb << 12) + (size_t)(valid ? g : 0)) * Cc + kk + k8 * 8;
        cp16z(adst + row * ROWB + k8 * 16, A + off, valid ? 16u : 0u);
    }
}

__device__ __forceinline__ void load_W_chunk(uint32_t wdst, const __half* __restrict__ W,
    int tap, int kk, int block_n, int tid)
{
#pragma unroll
    for (int q = 0; q < 4; q++) {
        int c   = tid + 256 * q;
        int row = c >> 3, k8 = c & 7;
        size_t off = ((size_t)(tap * Cc + block_n + row)) * Cc + kk + k8 * 8;
        cp16(wdst + row * ROWB + k8 * 16, W + off);
    }
}

template <bool OUT_HALF, bool RES_HALF>
__global__ void __launch_bounds__(256, 2)
conv_mma_kernel(const __half* __restrict__ A, const __half* __restrict__ W,
                const float* __restrict__ bias, const void* __restrict__ res,
                void* __restrict__ out, float* __restrict__ statsPart, int dil)
{
    extern __shared__ __align__(16) char dsm[];
    const uint32_t sbase = smem_u32(dsm);
    const uint32_t a0 = sbase, a1 = sbase + A_STAGE;
    const uint32_t w0 = sbase + 2 * A_STAGE, w1 = w0 + W_STAGE;

    const int tid  = threadIdx.x;
    const int wid  = tid >> 5;
    const int lane = tid & 31;

    const int block_m = blockIdx.x * 128;
    const int block_n = blockIdx.y * 128;
    const int bb = block_m >> 12;
    const int t0 = block_m & (Tt - 1);

    const int wm = (wid >> 2) * 64;   // warp m offset (0 or 64)
    const int wn = (wid & 3) * 32;    // warp n offset (0..96)

    float acc[4][4][4];
#pragma unroll
    for (int i = 0; i < 4; i++)
#pragma unroll
        for (int j = 0; j < 4; j++)
#pragma unroll
            for (int r = 0; r < 4; r++) acc[i][j][r] = 0.f;

    // prologue: A chunk 0 + W(k=0, tap=0)
    load_A_chunk(a0, A, bb, t0, 0, dil, tid);
    load_W_chunk(w0, W, 0, 0, block_n, tid);
    CP_COMMIT();

    int k = 0, tap = 0;
    for (int s = 0; s < 24; ++s) {
        // prefetch stage s+1
        if (s + 1 < 24) {
            int tap1 = tap + 1, k1 = k;
            if (tap1 == 3) { tap1 = 0; k1 = k + 1; }
            if (tap1 == 0)
                load_A_chunk((k1 & 1) ? a1 : a0, A, bb, t0, k1 * 64, dil, tid);
            load_W_chunk(((s + 1) & 1) ? w1 : w0, W, tap1, k1 * 64, block_n, tid);
            CP_COMMIT();
            CP_WAIT1();
        } else {
            CP_WAIT0();
        }
        __syncthreads();

        const uint32_t sA = (k & 1) ? a1 : a0;
        const uint32_t sW = (s & 1) ? w1 : w0;
        const int rowoff = tap * dil;    // shift into the A superset

        const int arow = lane & 15;
        const int ahalf = (lane >> 4) * 8;
        const int bn = (lane & 7) + ((lane >> 4) & 1) * 8;
        const int bk = ((lane >> 3) & 1) * 8;

#pragma unroll
        for (int ks = 0; ks < 4; ++ks) {
            const int kc = ks * 16;
            uint32_t ah[4][4], bh[2][4];
#pragma unroll
            for (int i = 0; i < 4; i++) {
                uint32_t aaddr = (uint32_t)((wm + i * 16 + arow + rowoff) * ROWB + (kc + ahalf) * 2);
                ldsm4(ah[i], sA + aaddr);
            }
#pragma unroll
            for (int j2 = 0; j2 < 2; j2++) {
                uint32_t baddr = (uint32_t)((wn + j2 * 16 + bn) * ROWB + (kc + bk) * 2);
                ldsm4(bh[j2], sW + baddr);
            }
#pragma unroll
            for (int i = 0; i < 4; i++)
#pragma unroll
                for (int j = 0; j < 4; j++)
                    mma16816(acc[i][j], ah[i], &bh[j >> 1][(j & 1) * 2]);
        }
        __syncthreads();

        if (++tap == 3) { tap = 0; ++k; }
    }

    // epilogue: bias (+ residual) + optional per-column stats partials
    float cs[4][2], cq[4][2];
#pragma unroll
    for (int j = 0; j < 4; j++) { cs[j][0] = cs[j][1] = cq[j][0] = cq[j][1] = 0.f; }

#pragma unroll
    for (int i = 0; i < 4; i++) {
#pragma unroll
        for (int j = 0; j < 4; j++) {
            const int col  = block_n + wn + j * 8 + (lane & 3) * 2;
            const int row0 = block_m + wm + i * 16 + (lane >> 2);
            const int row1 = row0 + 8;
            const float b0 = bias[col], b1 = bias[col + 1];

            float2 v0 = make_float2(acc[i][j][0] + b0, acc[i][j][1] + b1);
            float2 v1 = make_float2(acc[i][j][2] + b0, acc[i][j][3] + b1);
            if (res) {
                if (RES_HALF) {
                    const __half* rh = (const __half*)res;
                    float2 r0 = __half22float2(*(const __half2*)(rh + (size_t)row0 * Cc + col));
                    float2 r1 = __half22float2(*(const __half2*)(rh + (size_t)row1 * Cc + col));
                    v0.x += r0.x; v0.y += r0.y;
                    v1.x += r1.x; v1.y += r1.y;
                } else {
                    const float* rf = (const float*)res;
                    float2 r0 = *(const float2*)(rf + (size_t)row0 * Cc + col);
                    float2 r1 = *(const float2*)(rf + (size_t)row1 * Cc + col);
                    v0.x += r0.x; v0.y += r0.y;
                    v1.x += r1.x; v1.y += r1.y;
                }
            }
            if (OUT_HALF) {
                __half* oh = (__half*)out;
                *(__half2*)(oh + (size_t)row0 * Cc + col) = __floats2half2_rn(v0.x, v0.y);
                *(__half2*)(oh + (size_t)row1 * Cc + col) = __floats2half2_rn(v1.x, v1.y);
            } else {
                float* of = (float*)out;
                *(float2*)(of + (size_t)row0 * Cc + col) = v0;
                *(float2*)(of + (size_t)row1 * Cc + col) = v1;
            }

            cs[j][0] += v0.x + v1.x;
            cs[j][1] += v0.y + v1.y;
            cq[j][0] += v0.x * v0.x + v1.x * v1.x;
            cq[j][1] += v0.y * v0.y + v1.y * v1.y;
        }
    }

    if (statsPart) {
#pragma unroll
        for (int j = 0; j < 4; j++)
#pragma unroll
            for (int k2 = 0; k2 < 2; k2++) {
#pragma unroll
                for (int off = 4; off < 32; off <<= 1) {
                    cs[j][k2] += __shfl_xor_sync(0xffffffffu, cs[j][k2], off);
                    cq[j][k2] += __shfl_xor_sync(0xffffffffu, cq[j][k2], off);
                }
            }
        float* ssum = (float*)dsm;          // [8][32]
        float* ssq  = ssum + 256;
        if (lane < 4) {
#pragma unroll
            for (int j = 0; j < 4; j++)
#pragma unroll
                for (int k2 = 0; k2 < 2; k2++) {
                    int cc = j * 8 + lane * 2 + k2;
                    ssum[wid * 32 + cc] = cs[j][k2];
                    ssq [wid * 32 + cc] = cq[j][k2];
                }
        }
        __syncthreads();
        const int si = (block_m >> 7) & 31;
        if (tid < 128) {
            int w = tid >> 5, cw = tid & 31;
            statsPart[((size_t)si * Bb + bb) * Cc + block_n + tid] =
                ssum[w * 32 + cw] + ssum[(w + 4) * 32 + cw];
        } else {
            int t2 = tid - 128;
            int w = t2 >> 5, cw = t2 & 31;
            statsPart[((size_t)(32 + si) * Bb + bb) * Cc + block_n + t2] =
                ssq[w * 32 + cw] + ssq[(w + 4) * 32 + cw];
        }
    }
}

// -------------------------------- launch --------------------------------------
extern "C" void kernel_launch(void* const* d_in, const int* in_sizes, int n_in,
                              void* d_out, int out_size)
{
    (void)in_sizes; (void)n_in; (void)out_size;
    const float* x      = (const float*)d_in[0];
    const float* s      = (const float*)d_in[1];
    const float* fc1w   = (const float*)d_in[2];
    const float* fc1b   = (const float*)d_in[3];
    const float* alpha1 = (const float*)d_in[4];
    const float* c1v    = (const float*)d_in[5];
    const float* c1g    = (const float*)d_in[6];
    const float* c1b    = (const float*)d_in[7];
    const float* fc2w   = (const float*)d_in[8];
    const float* fc2b   = (const float*)d_in[9];
    const float* alpha2 = (const float*)d_in[10];
    const float* c2v    = (const float*)d_in[11];
    const float* c2g    = (const float*)d_in[12];
    const float* c2b    = (const float*)d_in[13];
    float* out = (float*)d_out;

    __half *A, *T2h, *X1h, *W;
    float *SC, *GB, *MU, *RS, *PS, *IA;
    cudaGetSymbolAddress((void**)&A,   g_A);
    cudaGetSymbolAddress((void**)&T2h, g_T2h);
    cudaGetSymbolAddress((void**)&X1h, g_X1h);
    cudaGetSymbolAddress((void**)&W,   g_W);
    cudaGetSymbolAddress((void**)&SC,  g_SC);
    cudaGetSymbolAddress((void**)&GB,  g_GB);
    cudaGetSymbolAddress((void**)&MU,  g_MU);
    cudaGetSymbolAddress((void**)&RS,  g_RS);
    cudaGetSymbolAddress((void**)&PS,  g_PS);
    cudaGetSymbolAddress((void**)&IA,  g_IA);

    cudaFuncSetAttribute(conv_mma_kernel<true, false>,
                         cudaFuncAttributeMaxDynamicSharedMemorySize, CONV_SMEM);
    cudaFuncSetAttribute(conv_mma_kernel<true, true>,
                         cudaFuncAttributeMaxDynamicSharedMemorySize, CONV_SMEM);
    cudaFuncSetAttribute(conv_mma_kernel<false, true>,
                         cudaFuncAttributeMaxDynamicSharedMemorySize, CONV_SMEM);

    // setup: style affines + weight-norm scale + inv-alpha (one kernel), transpose
    setup_kernel<<<54, 512>>>(s, fc1w, fc1b, fc2w, fc2b,
                              c1v, c1g, c2v, c2g, alpha1, alpha2, GB, SC, IA);
    wtrans_kernel<<<dim3(16, 16, 18), dim3(32, 8)>>>(c1v, c2v, SC, W);

    const int dils[3] = {1, 3, 5};
    const size_t N4 = (size_t)Bb * Tt * Cc / 4;
    const int ew_blocks = (int)(N4 / 1024);         // 4 float4 per thread
    dim3 conv_grid((Bb * Tt) / 128, Cc / 128);
    const size_t KCC = (size_t)Kt * Cc * Cc;

    // initial stats on x
    initstats_kernel<<<dim3(128, Bb), 512>>>(x, PS);
    finalize_kernel<128><<<64, 256>>>(PS, MU, RS);

    for (int i = 0; i < 3; i++) {
        // ---- layer 1: adain -> conv(dil) into T2h (+stats) ----
        if (i == 0)
            adain_snake_kernel<false><<<ew_blocks, 256>>>(x, MU, RS,
                    GB + (size_t)(2 * i) * Bb * 2 * Cc,
                    alpha1 + (size_t)i * Cc, IA + (size_t)(2 * i) * Cc, A);
        else
            adain_snake_kernel<true><<<ew_blocks, 256>>>(X1h, MU, RS,
                    GB + (size_t)(2 * i) * Bb * 2 * Cc,
                    alpha1 + (size_t)i * Cc, IA + (size_t)(2 * i) * Cc, A);

        conv_mma_kernel<true, false><<<conv_grid, 256, CONV_SMEM>>>(A,
                W + (size_t)(2 * i) * KCC, c1b + (size_t)i * Cc,
                (const void*)0, T2h, PS, dils[i]);
        finalize_kernel<32><<<64, 256>>>(PS, MU, RS);

        // ---- layer 2: adain -> conv(1) + residual ----
        adain_snake_kernel<true><<<ew_blocks, 256>>>(T2h, MU, RS,
                GB + (size_t)(2 * i + 1) * Bb * 2 * Cc,
                alpha2 + (size_t)i * Cc, IA + (size_t)(2 * i + 1) * Cc, A);

        if (i == 0) {
            conv_mma_kernel<true, false><<<conv_grid, 256, CONV_SMEM>>>(A,
                    W + (size_t)(2 * i + 1) * KCC, c2b + (size_t)i * Cc,
                    (const void*)x, X1h, PS, 1);
            finalize_kernel<32><<<64, 256>>>(PS, MU, RS);
        } else if (i == 1) {
            conv_mma_kernel<true, true><<<conv_grid, 256, CONV_SMEM>>>(A,
                    W + (size_t)(2 * i + 1) * KCC, c2b + (size_t)i * Cc,
                    (const void*)X1h, X1h, PS, 1);
            finalize_kernel<32><<<64, 256>>>(PS, MU, RS);
        } else {
            conv_mma_kernel<false, true><<<conv_grid, 256, CONV_SMEM>>>(A,
                    W + (size_t)(2 * i + 1) * KCC, c2b + (size_t)i * Cc,
                    (const void*)X1h, out, (float*)0, 1);
        }
    }
}